// round 12
// baseline (speedup 1.0000x reference)
#include <cuda_runtime.h>
#include <cuda_fp16.h>

#define NA 4096
#define H  64
#define OD 48
#define NSEG 48
#define PC (NSEG * OD)    /* 2304 logical cols */
#define PCP (NSEG * 64)   /* 3072 padded cols: 128B slot per segment */
#define PROWB 6144u       /* bytes per padded fp16 P row */

// Scratch (device globals: allocation-free rule). Tail pad: sentinel (s=48)
// on the last row reads the first 128B past the array.
__device__ __align__(128) __half g_P[(size_t)NA * PCP + 64];  // 25.2 MB
__device__ float         g_Wt[H * PC];               // 589 KB reshaped weights
__device__ unsigned char g_seg[(size_t)NA * NA];     // 16.7 MB seg ids
__device__ float         g_invc[NA * 64];            // 1/count per (i,s), 0-pad

// ---------------------------------------------------------------------------
// Zero the 32B pad of every 128B slot (lanes 24-31 of k_main read them).
// ---------------------------------------------------------------------------
__global__ void k_zpad() {
    int idx = blockIdx.x * blockDim.x + threadIdx.x;   // NA*NSEG slots
    if (idx >= NA * NSEG) return;
    int j = idx / NSEG, s = idx - j * NSEG;
    uint4 z = make_uint4(0, 0, 0, 0);
    uint4* p = (uint4*)((char*)g_P + (size_t)j * PROWB + s * 128 + 96);
    p[0] = z; p[1] = z;
}

// ---------------------------------------------------------------------------
// Wt[k][s*48+o] = fc_w[o, s*64+k];  also zero the g_P tail pad.
// ---------------------------------------------------------------------------
__global__ void k_reshape(const float* __restrict__ fw) {
    int idx = blockIdx.x * blockDim.x + threadIdx.x;
    if (idx < 64) g_P[(size_t)NA * PCP + idx] = __float2half(0.f);
    if (idx >= H * PC) return;
    int k = idx / PC, c = idx - k * PC;
    int s = c / OD, o = c - s * OD;
    g_Wt[idx] = fw[o * (NSEG * H) + s * H + k];
}

// ---------------------------------------------------------------------------
// P[j][s*64+o] = sum_k hidden[j][k] * Wt[k][s*48+o]  (padded store layout)
// ---------------------------------------------------------------------------
#define GR 8
__global__ __launch_bounds__(256) void k_gemmP(const float* __restrict__ hidden) {
    __shared__ float sh[GR][H];
    int t = threadIdx.x;
    int jb = blockIdx.x * GR;
    for (int idx = t; idx < GR * H; idx += 256)
        sh[idx >> 6][idx & 63] = hidden[jb * H + idx];
    __syncthreads();

    int poff[9];
#pragma unroll
    for (int u = 0; u < 9; u++) {
        int col = u * 256 + t;
        int s = col / OD, o = col - s * OD;
        poff[u] = s * 64 + o;
    }

    float acc[GR][9];
#pragma unroll
    for (int j = 0; j < GR; j++)
#pragma unroll
        for (int u = 0; u < 9; u++) acc[j][u] = 0.f;

    for (int k = 0; k < H; k++) {
        float w[9];
#pragma unroll
        for (int u = 0; u < 9; u++) w[u] = g_Wt[k * PC + u * 256 + t];
#pragma unroll
        for (int j = 0; j < GR; j++) {
            float hv = sh[j][k];
#pragma unroll
            for (int u = 0; u < 9; u++) acc[j][u] = fmaf(hv, w[u], acc[j][u]);
        }
    }
#pragma unroll
    for (int j = 0; j < GR; j++)
#pragma unroll
        for (int u = 0; u < 9; u++)
            g_P[(size_t)(jb + j) * PCP + poff[u]] = __float2half_rn(acc[j][u]);
}

// ---------------------------------------------------------------------------
// seg(i,j): MUFU-free (ring via r^2 thresholds, wedge via octant compares,
// exactly replicating trunc(atan2*4/pi + 3) mod 8). 48 = invalid sentinel.
// ---------------------------------------------------------------------------
__device__ __forceinline__ int seg_of(float xi, float yi, float xj, float yj) {
    float dx = xj - xi, dy = yj - yi;
    float r2 = fmaf(dx, dx, dy * dy);
    if (r2 < 0.25f)          return NSEG;
    if (r2 >= 36.75834735f)  return NSEG;
    int ring = (r2 >= 0.574349177f) + (r2 >= 1.319507911f) + (r2 >= 3.031433132f)
             + (r2 >= 6.964404507f) + (r2 >= 16.0f);
    int w;
    if (dy > 0.f) {
        if (dx > 0.f)      w = (dy <  dx) ? 3 : 4;
        else if (dx < 0.f) w = (dy > -dx) ? 5 : 6;
        else               w = 5;
    } else if (dy < 0.f) {
        if (dx > 0.f)      w = (-dy <= dx) ? 2 : 1;
        else if (dx < 0.f) w = 0;
        else               w = 1;
    } else {
        w = (dx >= 0.f) ? 3 : 7;
    }
    return ring * 8 + w;
}

// ---------------------------------------------------------------------------
// k_seg: warp per i. Computes g_seg[i][j] (u8) and g_invc[i][s] (1/count).
// ---------------------------------------------------------------------------
__global__ __launch_bounds__(256) void k_seg(const float2* __restrict__ yp) {
    __shared__ unsigned short hist[8][48 * 33];
    int wp = threadIdx.x >> 5, lane = threadIdx.x & 31;
    int i = blockIdx.x * 8 + wp;
    float2 pi = yp[i];

    for (int idx = lane; idx < 48 * 33; idx += 32) hist[wp][idx] = 0;
    __syncwarp();

    unsigned char* segrow = g_seg + (size_t)i * NA;
    for (int base = 0; base < NA; base += 32) {
        float2 pj = yp[base + lane];
        int s = seg_of(pi.x, pi.y, pj.x, pj.y);
        segrow[base + lane] = (unsigned char)s;
        if (s < NSEG) hist[wp][s * 33 + lane]++;
    }
    __syncwarp();
    for (int s = lane; s < 64; s += 32) {
        float w = 0.f;
        if (s < NSEG) {
            unsigned c = 0;
#pragma unroll
            for (int k = 0; k < 32; k++) c += hist[wp][s * 33 + k];
            w = (c > 0) ? (1.0f / (float)c) : 0.0f;
        }
        g_invc[i * 64 + s] = w;
    }
}

// ---------------------------------------------------------------------------
// k_main: warp per i. ONE pair per step, all 32 lanes in the pair's single
// 128B slot (uniform-line LDG.32 = 1 wavefront, vs 4-line divergent LDG.128
// at 2.07 cyc/line in R11). Lane l owns outputs {2l, 2l+1}; lanes 24-31 read
// the zeroed pad and are discarded. Seg ids read as packed u32 (4 pairs/word).
// Batch 8 pairs per unrolled step for MLP.
// ---------------------------------------------------------------------------
#define UNR 8
__global__ __launch_bounds__(256, 4) void k_main(const float* __restrict__ fb,
                                                 float* __restrict__ out) {
    __shared__ float         wtab[8][64];
    __shared__ unsigned char segbuf[8][1024];
    int wp = threadIdx.x >> 5, lane = threadIdx.x & 31;
    int i = blockIdx.x * 8 + wp;

    for (int s = lane; s < 64; s += 32) wtab[wp][s] = g_invc[i * 64 + s];
    __syncwarp();

    const unsigned char* Pb = (const unsigned char*)g_P + (unsigned)(lane * 4);
    float a0 = 0.f, a1 = 0.f, b0 = 0.f, b1 = 0.f;
    const unsigned char* segrow = g_seg + (size_t)i * NA;

    for (int c0 = 0; c0 < NA; c0 += 1024) {
        const uint4* src = (const uint4*)(segrow + c0);
        uint4* dst = (uint4*)segbuf[wp];
        dst[lane]      = src[lane];
        dst[lane + 32] = src[lane + 32];
        __syncwarp();

        const unsigned char* rp = Pb + (size_t)c0 * PROWB;
        const unsigned int* sw = (const unsigned int*)segbuf[wp];
        for (int t0 = 0; t0 < 1024; t0 += UNR) {
            unsigned int wa = sw[t0 >> 2];
            unsigned int wb = sw[(t0 >> 2) + 1];
            int sv[UNR];
            sv[0] =  wa        & 0xFF;  sv[1] = (wa >> 8) & 0xFF;
            sv[2] = (wa >> 16) & 0xFF;  sv[3] =  wa >> 24;
            sv[4] =  wb        & 0xFF;  sv[5] = (wb >> 8) & 0xFF;
            sv[6] = (wb >> 16) & 0xFF;  sv[7] =  wb >> 24;
            float wv[UNR];
#pragma unroll
            for (int u = 0; u < UNR; u++) wv[u] = wtab[wp][sv[u]];
            unsigned int vv[UNR];
#pragma unroll
            for (int u = 0; u < UNR; u++)
                vv[u] = *(const unsigned int*)(rp + (unsigned)u * PROWB
                                                  + ((unsigned)sv[u] << 7));
#pragma unroll
            for (int u = 0; u < UNR; u++) {
                float2 f = __half22float2(*(const __half2*)&vv[u]);
                if (u & 1) { b0 = fmaf(wv[u], f.x, b0); b1 = fmaf(wv[u], f.y, b1); }
                else       { a0 = fmaf(wv[u], f.x, a0); a1 = fmaf(wv[u], f.y, a1); }
            }
            rp += UNR * PROWB;
        }
        __syncwarp();
    }
    a0 += b0; a1 += b1;

    if (lane < 24) {
        float2 bias = ((const float2*)fb)[lane];
        float2 r = make_float2(fmaxf(a0 + bias.x, 0.f), fmaxf(a1 + bias.y, 0.f));
        *(float2*)(out + i * OD + 2 * lane) = r;
    }
}

// ---------------------------------------------------------------------------
extern "C" void kernel_launch(void* const* d_in, const int* in_sizes, int n_in,
                              void* d_out, int out_size) {
    const float* ypred  = (const float*)d_in[0];
    const float* hidden = (const float*)d_in[1];
    const float* fc_w   = (const float*)d_in[2];
    const float* fc_b   = (const float*)d_in[3];
    float* out = (float*)d_out;

    k_zpad<<<(NA * NSEG + 255) / 256, 256>>>();
    k_reshape<<<(H * PC + 255) / 256, 256>>>(fc_w);
    k_gemmP<<<NA / GR, 256>>>(hidden);
    k_seg<<<NA / 8, 256>>>((const float2*)ypred);
    k_main<<<NA / 8, 256>>>(fc_b, out);
}

// round 13
// speedup vs baseline: 1.6619x; 1.6619x over previous
#include <cuda_runtime.h>
#include <cuda_fp16.h>

#define NA 4096
#define H  64
#define OD 48
#define NSEG 48
#define PC (NSEG * OD)    /* 2304 logical cols */
#define PCP (NSEG * 64)   /* 3072 padded cols: 128B slot per segment */
#define PROWB 6144u       /* bytes per padded fp16 P row */
#define IPB 28            /* i's (warps) per k_main block: 1 block/SM */

// Scratch (device globals: allocation-free rule). Tail pad: sentinel (s=48)
// on the last row reads the first 128B past the array.
__device__ __align__(128) __half g_P[(size_t)NA * PCP + 64];  // 25.2 MB
__device__ float         g_Wt[H * PC];               // 589 KB reshaped weights
__device__ unsigned char g_seg[(size_t)NA * NA];     // 16.7 MB seg ids
__device__ float         g_invc[NA * 64];            // 1/count per (i,s), 0-pad

// ---------------------------------------------------------------------------
// Wt[k][s*48+o] = fc_w[o, s*64+k];  also zero the g_P tail pad.
// ---------------------------------------------------------------------------
__global__ void k_reshape(const float* __restrict__ fw) {
    int idx = blockIdx.x * blockDim.x + threadIdx.x;
    if (idx < 64) g_P[(size_t)NA * PCP + idx] = __float2half(0.f);
    if (idx >= H * PC) return;
    int k = idx / PC, c = idx - k * PC;
    int s = c / OD, o = c - s * OD;
    g_Wt[idx] = fw[o * (NSEG * H) + s * H + k];
}

// ---------------------------------------------------------------------------
// P[j][s*64+o] = sum_k hidden[j][k] * Wt[k][s*48+o]  (padded store layout)
// ---------------------------------------------------------------------------
#define GR 8
__global__ __launch_bounds__(256) void k_gemmP(const float* __restrict__ hidden) {
    __shared__ float sh[GR][H];
    int t = threadIdx.x;
    int jb = blockIdx.x * GR;
    for (int idx = t; idx < GR * H; idx += 256)
        sh[idx >> 6][idx & 63] = hidden[jb * H + idx];
    __syncthreads();

    int poff[9];
#pragma unroll
    for (int u = 0; u < 9; u++) {
        int col = u * 256 + t;
        int s = col / OD, o = col - s * OD;
        poff[u] = s * 64 + o;
    }

    float acc[GR][9];
#pragma unroll
    for (int j = 0; j < GR; j++)
#pragma unroll
        for (int u = 0; u < 9; u++) acc[j][u] = 0.f;

    for (int k = 0; k < H; k++) {
        float w[9];
#pragma unroll
        for (int u = 0; u < 9; u++) w[u] = g_Wt[k * PC + u * 256 + t];
#pragma unroll
        for (int j = 0; j < GR; j++) {
            float hv = sh[j][k];
#pragma unroll
            for (int u = 0; u < 9; u++) acc[j][u] = fmaf(hv, w[u], acc[j][u]);
        }
    }
#pragma unroll
    for (int j = 0; j < GR; j++)
#pragma unroll
        for (int u = 0; u < 9; u++)
            g_P[(size_t)(jb + j) * PCP + poff[u]] = __float2half_rn(acc[j][u]);
}

// ---------------------------------------------------------------------------
// seg(i,j): MUFU-free AND branch-free (pure FSETP/SEL chain; semantics
// identical to the nested-if version: replicates trunc(atan2*4/pi+3) mod 8
// and the ring thresholds). 48 = invalid sentinel.
// ---------------------------------------------------------------------------
__device__ __forceinline__ int seg_of(float xi, float yi, float xj, float yj) {
    float dx = xj - xi, dy = yj - yi;
    float r2 = fmaf(dx, dx, dy * dy);
    int ring = (r2 >= 0.574349177f) + (r2 >= 1.319507911f) + (r2 >= 3.031433132f)
             + (r2 >= 6.964404507f) + (r2 >= 16.0f);
    int wpp = (dy <  dx)  ? 3 : 4;
    int wpn = (dy > -dx)  ? 5 : 6;
    int wp  = (dx > 0.f) ? wpp : ((dx < 0.f) ? wpn : 5);
    int wnp = (-dy <= dx) ? 2 : 1;
    int wn  = (dx > 0.f) ? wnp : ((dx < 0.f) ? 0 : 1);
    int wz  = (dx >= 0.f) ? 3 : 7;
    int w   = (dy > 0.f) ? wp : ((dy < 0.f) ? wn : wz);
    bool valid = (r2 >= 0.25f) & (r2 < 36.75834735f);
    return valid ? (ring * 8 + w) : NSEG;
}

// ---------------------------------------------------------------------------
// k_seg: warp per i. g_seg[i][j] (u8) + g_invc[i][s] (1/count).
// Unconditional histogram (49 rows; s=48 row ignored) -> no branches at all.
// ---------------------------------------------------------------------------
__global__ __launch_bounds__(256) void k_seg(const float2* __restrict__ yp) {
    __shared__ unsigned short hist[8][49 * 33];
    int wp = threadIdx.x >> 5, lane = threadIdx.x & 31;
    int i = blockIdx.x * 8 + wp;
    float2 pi = yp[i];

    for (int idx = lane; idx < 49 * 33; idx += 32) hist[wp][idx] = 0;
    __syncwarp();

    unsigned char* segrow = g_seg + (size_t)i * NA;
    for (int base = 0; base < NA; base += 32) {
        float2 pj = yp[base + lane];
        int s = seg_of(pi.x, pi.y, pj.x, pj.y);
        segrow[base + lane] = (unsigned char)s;
        hist[wp][s * 33 + lane]++;            // s=48 lands in ignored row
    }
    __syncwarp();
    for (int s = lane; s < 64; s += 32) {
        float w = 0.f;
        if (s < NSEG) {
            unsigned c = 0;
#pragma unroll
            for (int k = 0; k < 32; k++) c += hist[wp][s * 33 + k];
            w = (c > 0) ? (1.0f / (float)c) : 0.0f;
        }
        g_invc[i * 64 + s] = w;
    }
}

// ---------------------------------------------------------------------------
// k_main: R11 gather body (4 pairs per LDG.128, batched unroll-8), but ONE
// 28-warp block per SM (147 blocks x 896 threads) for uniform SM load —
// R11's 512-block grid left 68 SMs with 32 warps vs 80 with 24 (+15% skew).
// Lanes 0-23 = 4 groups of 6 (group g -> pair 4t+g, sub owns outs sub*8..+7);
// lanes 24-31 mirror group 0's lines (no extra sectors).
// ---------------------------------------------------------------------------
#define UNR 8
__global__ __launch_bounds__(IPB * 32, 1) void k_main(const float* __restrict__ fb,
                                                      float* __restrict__ out) {
    __shared__ float         wtab[IPB][64];
    __shared__ unsigned char segbuf[IPB][1024];
    int wp = threadIdx.x >> 5, lane = threadIdx.x & 31;
    int i = blockIdx.x * IPB + wp;
    if (i >= NA) return;                       // warp-uniform exit

    for (int s = lane; s < 64; s += 32) wtab[wp][s] = g_invc[i * 64 + s];
    __syncwarp();

    int grp = (lane < 24) ? (lane / 6) : 0;
    int sub = (lane < 24) ? (lane - grp * 6) : ((lane - 24) % 6);
    const unsigned char* Pb = (const unsigned char*)g_P + (unsigned)(sub * 16);

    float a0 = 0.f, a1 = 0.f, a2 = 0.f, a3 = 0.f;
    float a4 = 0.f, a5 = 0.f, a6 = 0.f, a7 = 0.f;
    const unsigned char* segrow = g_seg + (size_t)i * NA;

    for (int c0 = 0; c0 < NA; c0 += 1024) {
        const uint4* src = (const uint4*)(segrow + c0);
        uint4* dst = (uint4*)segbuf[wp];
        dst[lane]      = src[lane];
        dst[lane + 32] = src[lane + 32];
        __syncwarp();

        const unsigned char* rp = Pb + (size_t)c0 * PROWB;
        for (int t0 = 0; t0 < 256; t0 += UNR) {
            int   sv[UNR];
            float wv[UNR];
            uint4 vv[UNR];
#pragma unroll
            for (int u = 0; u < UNR; u++)
                sv[u] = segbuf[wp][4 * (t0 + u) + grp];     // 8x LDS.U8
#pragma unroll
            for (int u = 0; u < UNR; u++)
                wv[u] = wtab[wp][sv[u]];                    // 8x LDS
#pragma unroll
            for (int u = 0; u < UNR; u++)
                vv[u] = *(const uint4*)(rp
                          + (unsigned)(4 * (t0 + u) + grp) * PROWB
                          + ((unsigned)sv[u] << 7));        // 8x LDG.128
#pragma unroll
            for (int u = 0; u < UNR; u++) {
                float w = wv[u];
                float2 f0 = __half22float2(*(const __half2*)&vv[u].x);
                float2 f1 = __half22float2(*(const __half2*)&vv[u].y);
                float2 f2 = __half22float2(*(const __half2*)&vv[u].z);
                float2 f3 = __half22float2(*(const __half2*)&vv[u].w);
                a0 = fmaf(w, f0.x, a0); a1 = fmaf(w, f0.y, a1);
                a2 = fmaf(w, f1.x, a2); a3 = fmaf(w, f1.y, a3);
                a4 = fmaf(w, f2.x, a4); a5 = fmaf(w, f2.y, a5);
                a6 = fmaf(w, f3.x, a6); a7 = fmaf(w, f3.y, a7);
            }
        }
        __syncwarp();
    }

    // combine 4 groups: round 1 (+6) -> g0+=g1, g2+=g3; round 2 (+12)
#pragma unroll
    for (int d = 6; d <= 12; d += 6) {
        a0 += __shfl_down_sync(0xffffffffu, a0, d);
        a1 += __shfl_down_sync(0xffffffffu, a1, d);
        a2 += __shfl_down_sync(0xffffffffu, a2, d);
        a3 += __shfl_down_sync(0xffffffffu, a3, d);
        a4 += __shfl_down_sync(0xffffffffu, a4, d);
        a5 += __shfl_down_sync(0xffffffffu, a5, d);
        a6 += __shfl_down_sync(0xffffffffu, a6, d);
        a7 += __shfl_down_sync(0xffffffffu, a7, d);
    }

    if (lane < 6) {
        const float4 b0 = ((const float4*)fb)[2 * lane];
        const float4 b1 = ((const float4*)fb)[2 * lane + 1];
        float4 r0, r1;
        r0.x = fmaxf(a0 + b0.x, 0.f); r0.y = fmaxf(a1 + b0.y, 0.f);
        r0.z = fmaxf(a2 + b0.z, 0.f); r0.w = fmaxf(a3 + b0.w, 0.f);
        r1.x = fmaxf(a4 + b1.x, 0.f); r1.y = fmaxf(a5 + b1.y, 0.f);
        r1.z = fmaxf(a6 + b1.z, 0.f); r1.w = fmaxf(a7 + b1.w, 0.f);
        float* op = out + i * OD + lane * 8;
        *(float4*)op       = r0;
        *(float4*)(op + 4) = r1;
    }
}

// ---------------------------------------------------------------------------
extern "C" void kernel_launch(void* const* d_in, const int* in_sizes, int n_in,
                              void* d_out, int out_size) {
    const float* ypred  = (const float*)d_in[0];
    const float* hidden = (const float*)d_in[1];
    const float* fc_w   = (const float*)d_in[2];
    const float* fc_b   = (const float*)d_in[3];
    float* out = (float*)d_out;

    k_reshape<<<(H * PC + 255) / 256, 256>>>(fc_w);
    k_gemmP<<<NA / GR, 256>>>(hidden);
    k_seg<<<NA / 8, 256>>>((const float2*)ypred);
    k_main<<<(NA + IPB - 1) / IPB, IPB * 32>>>(fc_b, out);
}

// round 16
// speedup vs baseline: 1.7044x; 1.0255x over previous
#include <cuda_runtime.h>
#include <cuda_fp16.h>

#define NA 4096
#define H  64
#define OD 48
#define NSEG 48
#define PC (NSEG * OD)    /* 2304 logical cols */
#define PCP (NSEG * 64)   /* 3072 padded cols: 128B slot per segment */
#define PROWB 6144u       /* bytes per padded fp16 P row */
#define IPB 28            /* i's (warps) per k_main block: 1 block/SM */

// Scratch (device globals: allocation-free rule). Tail pad: sentinel (s=48)
// on the last row reads the first 128B past the array.
__device__ __align__(128) __half g_P[(size_t)NA * PCP + 64];  // 25.2 MB
__device__ float         g_Wt[H * PC];               // 589 KB reshaped weights
__device__ unsigned char g_seg[(size_t)NA * NA];     // 16.7 MB seg ids
__device__ float         g_invc[NA * 64];            // 1/count per (i,s), 0-pad

// ---------------------------------------------------------------------------
// Wt[k][s*48+o] = fc_w[o, s*64+k];  also zero the g_P tail pad.
// ---------------------------------------------------------------------------
__global__ void k_reshape(const float* __restrict__ fw) {
    int idx = blockIdx.x * blockDim.x + threadIdx.x;
    if (idx < 64) g_P[(size_t)NA * PCP + idx] = __float2half(0.f);
    if (idx >= H * PC) return;
    int k = idx / PC, c = idx - k * PC;
    int s = c / OD, o = c - s * OD;
    g_Wt[idx] = fw[o * (NSEG * H) + s * H + k];
}

// ---------------------------------------------------------------------------
// seg(i,j): MUFU-free AND branch-free (pure FSETP/SEL chain; replicates
// trunc(atan2*4/pi+3) mod 8 + ring thresholds). 48 = invalid sentinel.
// ---------------------------------------------------------------------------
__device__ __forceinline__ int seg_of(float xi, float yi, float xj, float yj) {
    float dx = xj - xi, dy = yj - yi;
    float r2 = fmaf(dx, dx, dy * dy);
    int ring = (r2 >= 0.574349177f) + (r2 >= 1.319507911f) + (r2 >= 3.031433132f)
             + (r2 >= 6.964404507f) + (r2 >= 16.0f);
    int wpp = (dy <  dx)  ? 3 : 4;
    int wpn = (dy > -dx)  ? 5 : 6;
    int wp  = (dx > 0.f) ? wpp : ((dx < 0.f) ? wpn : 5);
    int wnp = (-dy <= dx) ? 2 : 1;
    int wn  = (dx > 0.f) ? wnp : ((dx < 0.f) ? 0 : 1);
    int wz  = (dx >= 0.f) ? 3 : 7;
    int w   = (dy > 0.f) ? wp : ((dy < 0.f) ? wn : wz);
    bool valid = (r2 >= 0.25f) & (r2 < 36.75834735f);
    return valid ? (ring * 8 + w) : NSEG;
}

// ---------------------------------------------------------------------------
// k_prep: fused gemmP (blocks 0..511) + k_seg (blocks 512..1023).
// The two halves are data-independent; fusing lets them overlap across SMs
// instead of serializing at a kernel boundary.
// ---------------------------------------------------------------------------
#define GR 8
__global__ __launch_bounds__(256) void k_prep(const float* __restrict__ hidden,
                                              const float2* __restrict__ yp) {
    __shared__ float          sh[GR][H];          // gemmP half
    __shared__ unsigned short hist[8][49 * 33];   // k_seg half
    int t = threadIdx.x;

    if (blockIdx.x < 512) {
        // ---------------- gemmP: P[j][s*64+o] = hidden[j] . Wt[:,s*48+o] ----
        int jb = blockIdx.x * GR;
        for (int idx = t; idx < GR * H; idx += 256)
            sh[idx >> 6][idx & 63] = hidden[jb * H + idx];
        __syncthreads();

        int poff[9];
#pragma unroll
        for (int u = 0; u < 9; u++) {
            int col = u * 256 + t;
            int s = col / OD, o = col - s * OD;
            poff[u] = s * 64 + o;
        }

        float acc[GR][9];
#pragma unroll
        for (int j = 0; j < GR; j++)
#pragma unroll
            for (int u = 0; u < 9; u++) acc[j][u] = 0.f;

        for (int k = 0; k < H; k++) {
            float w[9];
#pragma unroll
            for (int u = 0; u < 9; u++) w[u] = g_Wt[k * PC + u * 256 + t];
#pragma unroll
            for (int j = 0; j < GR; j++) {
                float hv = sh[j][k];
#pragma unroll
                for (int u = 0; u < 9; u++) acc[j][u] = fmaf(hv, w[u], acc[j][u]);
            }
        }
#pragma unroll
        for (int j = 0; j < GR; j++)
#pragma unroll
            for (int u = 0; u < 9; u++)
                g_P[(size_t)(jb + j) * PCP + poff[u]] = __float2half_rn(acc[j][u]);
    } else {
        // ---------------- k_seg: g_seg[i][j] + g_invc[i][s] ----------------
        int wp = t >> 5, lane = t & 31;
        int i = (blockIdx.x - 512) * 8 + wp;
        float2 pi = yp[i];

        for (int idx = lane; idx < 49 * 33; idx += 32) hist[wp][idx] = 0;
        __syncwarp();

        unsigned char* segrow = g_seg + (size_t)i * NA;
        for (int base = 0; base < NA; base += 32) {
            float2 pj = yp[base + lane];
            int s = seg_of(pi.x, pi.y, pj.x, pj.y);
            segrow[base + lane] = (unsigned char)s;
            hist[wp][s * 33 + lane]++;          // s=48 row ignored
        }
        __syncwarp();
        for (int s = lane; s < 64; s += 32) {
            float w = 0.f;
            if (s < NSEG) {
                unsigned c = 0;
#pragma unroll
                for (int k = 0; k < 32; k++) c += hist[wp][s * 33 + k];
                w = (c > 0) ? (1.0f / (float)c) : 0.0f;
            }
            g_invc[i * 64 + s] = w;
        }
    }
}

// ---------------------------------------------------------------------------
// k_main: 4 pairs per LDG.128, batched unroll-8, one 28-warp block per SM.
// Seg ids fetched as 2 broadcast LDS.128 per 8-pair step (32B window) with
// shift/mask byte extraction — replaces 8 LDS.U8 (~15% of L1 wf bill).
// Lanes 0-23 = 4 groups of 6 (group g -> pair 4t+g, sub owns outs sub*8..+7);
// lanes 24-31 mirror group 0's lines (no extra sectors).
// ---------------------------------------------------------------------------
#define UNR 8
__global__ __launch_bounds__(IPB * 32, 1) void k_main(const float* __restrict__ fb,
                                                      float* __restrict__ out) {
    __shared__ float         wtab[IPB][64];
    __shared__ unsigned char segbuf[IPB][1024];
    int wp = threadIdx.x >> 5, lane = threadIdx.x & 31;
    int i = blockIdx.x * IPB + wp;
    if (i >= NA) return;                       // warp-uniform exit

    for (int s = lane; s < 64; s += 32) wtab[wp][s] = g_invc[i * 64 + s];
    __syncwarp();

    int grp = (lane < 24) ? (lane / 6) : 0;
    int sub = (lane < 24) ? (lane - grp * 6) : ((lane - 24) % 6);
    int shft = grp * 8;
    const unsigned char* Pb = (const unsigned char*)g_P + (unsigned)(sub * 16);

    float a0 = 0.f, a1 = 0.f, a2 = 0.f, a3 = 0.f;
    float a4 = 0.f, a5 = 0.f, a6 = 0.f, a7 = 0.f;
    const unsigned char* segrow = g_seg + (size_t)i * NA;

    for (int c0 = 0; c0 < NA; c0 += 1024) {
        const uint4* src = (const uint4*)(segrow + c0);
        uint4* dst = (uint4*)segbuf[wp];
        dst[lane]      = src[lane];
        dst[lane + 32] = src[lane + 32];
        __syncwarp();

        const unsigned char* rp = Pb + (size_t)c0 * PROWB;
        for (int t0 = 0; t0 < 256; t0 += UNR) {
            // 32 seg bytes for pairs 4*t0 .. 4*t0+31: 2 broadcast LDS.128
            const uint4* sp = (const uint4*)(segbuf[wp] + 4 * t0);
            uint4 sw0 = sp[0], sw1 = sp[1];
            int sv[UNR];
            sv[0] = (sw0.x >> shft) & 0xFF;  sv[1] = (sw0.y >> shft) & 0xFF;
            sv[2] = (sw0.z >> shft) & 0xFF;  sv[3] = (sw0.w >> shft) & 0xFF;
            sv[4] = (sw1.x >> shft) & 0xFF;  sv[5] = (sw1.y >> shft) & 0xFF;
            sv[6] = (sw1.z >> shft) & 0xFF;  sv[7] = (sw1.w >> shft) & 0xFF;
            float wv[UNR];
#pragma unroll
            for (int u = 0; u < UNR; u++)
                wv[u] = wtab[wp][sv[u]];                    // 8x LDS
            uint4 vv[UNR];
#pragma unroll
            for (int u = 0; u < UNR; u++)
                vv[u] = *(const uint4*)(rp
                          + (unsigned)(4 * (t0 + u) + grp) * PROWB
                          + ((unsigned)sv[u] << 7));        // 8x LDG.128
#pragma unroll
            for (int u = 0; u < UNR; u++) {
                float w = wv[u];
                float2 f0 = __half22float2(*(const __half2*)&vv[u].x);
                float2 f1 = __half22float2(*(const __half2*)&vv[u].y);
                float2 f2 = __half22float2(*(const __half2*)&vv[u].z);
                float2 f3 = __half22float2(*(const __half2*)&vv[u].w);
                a0 = fmaf(w, f0.x, a0); a1 = fmaf(w, f0.y, a1);
                a2 = fmaf(w, f1.x, a2); a3 = fmaf(w, f1.y, a3);
                a4 = fmaf(w, f2.x, a4); a5 = fmaf(w, f2.y, a5);
                a6 = fmaf(w, f3.x, a6); a7 = fmaf(w, f3.y, a7);
            }
        }
        __syncwarp();
    }

    // combine 4 groups: round 1 (+6) -> g0+=g1, g2+=g3; round 2 (+12)
#pragma unroll
    for (int d = 6; d <= 12; d += 6) {
        a0 += __shfl_down_sync(0xffffffffu, a0, d);
        a1 += __shfl_down_sync(0xffffffffu, a1, d);
        a2 += __shfl_down_sync(0xffffffffu, a2, d);
        a3 += __shfl_down_sync(0xffffffffu, a3, d);
        a4 += __shfl_down_sync(0xffffffffu, a4, d);
        a5 += __shfl_down_sync(0xffffffffu, a5, d);
        a6 += __shfl_down_sync(0xffffffffu, a6, d);
        a7 += __shfl_down_sync(0xffffffffu, a7, d);
    }

    if (lane < 6) {
        const float4 b0 = ((const float4*)fb)[2 * lane];
        const float4 b1 = ((const float4*)fb)[2 * lane + 1];
        float4 r0, r1;
        r0.x = fmaxf(a0 + b0.x, 0.f); r0.y = fmaxf(a1 + b0.y, 0.f);
        r0.z = fmaxf(a2 + b0.z, 0.f); r0.w = fmaxf(a3 + b0.w, 0.f);
        r1.x = fmaxf(a4 + b1.x, 0.f); r1.y = fmaxf(a5 + b1.y, 0.f);
        r1.z = fmaxf(a6 + b1.z, 0.f); r1.w = fmaxf(a7 + b1.w, 0.f);
        float* op = out + i * OD + lane * 8;
        *(float4*)op       = r0;
        *(float4*)(op + 4) = r1;
    }
}

// ---------------------------------------------------------------------------
extern "C" void kernel_launch(void* const* d_in, const int* in_sizes, int n_in,
                              void* d_out, int out_size) {
    const float* ypred  = (const float*)d_in[0];
    const float* hidden = (const float*)d_in[1];
    const float* fc_w   = (const float*)d_in[2];
    const float* fc_b   = (const float*)d_in[3];
    float* out = (float*)d_out;

    k_reshape<<<(H * PC + 255) / 256, 256>>>(fc_w);
    k_prep<<<1024, 256>>>(hidden, (const float2*)ypred);
    k_main<<<(NA + IPB - 1) / IPB, IPB * 32>>>(fc_b, out);
}

// round 17
// speedup vs baseline: 1.7111x; 1.0039x over previous
#include <cuda_runtime.h>
#include <cuda_fp16.h>

#define NA 4096
#define H  64
#define OD 48
#define NSEG 48
#define PC (NSEG * OD)    /* 2304 logical cols */
#define PCP (NSEG * 64)   /* 3072 padded cols: 128B slot per segment */
#define PROWB 6144u       /* bytes per padded fp16 P row */
#define IPB 28            /* i's (warps) per k_main block: 1 block/SM */

// Scratch (device globals: allocation-free rule). Tail pad: sentinel (s=48)
// on the last row reads the first 128B past the array.
__device__ __align__(128) __half g_P[(size_t)NA * PCP + 64];  // 25.2 MB
__device__ float         g_Wt[H * PC];               // 589 KB reshaped weights
__device__ unsigned char g_seg[(size_t)NA * NA];     // 16.7 MB seg ids
__device__ float         g_invc[NA * 64];            // 1/count per (i,s), 0-pad

// ---------------------------------------------------------------------------
// Wt[k][s*48+o] = fc_w[o, s*64+k];  also zero the g_P tail pad.
// ---------------------------------------------------------------------------
__global__ void k_reshape(const float* __restrict__ fw) {
    int idx = blockIdx.x * blockDim.x + threadIdx.x;
    if (idx < 64) g_P[(size_t)NA * PCP + idx] = __float2half(0.f);
    if (idx >= H * PC) return;
    int k = idx / PC, c = idx - k * PC;
    int s = c / OD, o = c - s * OD;
    g_Wt[idx] = fw[o * (NSEG * H) + s * H + k];
}

// ---------------------------------------------------------------------------
// seg(i,j): MUFU-free AND branch-free (pure FSETP/SEL chain; replicates
// trunc(atan2*4/pi+3) mod 8 + ring thresholds). 48 = invalid sentinel.
// ---------------------------------------------------------------------------
__device__ __forceinline__ int seg_of(float xi, float yi, float xj, float yj) {
    float dx = xj - xi, dy = yj - yi;
    float r2 = fmaf(dx, dx, dy * dy);
    int ring = (r2 >= 0.574349177f) + (r2 >= 1.319507911f) + (r2 >= 3.031433132f)
             + (r2 >= 6.964404507f) + (r2 >= 16.0f);
    int wpp = (dy <  dx)  ? 3 : 4;
    int wpn = (dy > -dx)  ? 5 : 6;
    int wp  = (dx > 0.f) ? wpp : ((dx < 0.f) ? wpn : 5);
    int wnp = (-dy <= dx) ? 2 : 1;
    int wn  = (dx > 0.f) ? wnp : ((dx < 0.f) ? 0 : 1);
    int wz  = (dx >= 0.f) ? 3 : 7;
    int w   = (dy > 0.f) ? wp : ((dy < 0.f) ? wn : wz);
    bool valid = (r2 >= 0.25f) & (r2 < 36.75834735f);
    return valid ? (ring * 8 + w) : NSEG;
}

// ---------------------------------------------------------------------------
// k_prep: fused gemmP (blocks 0..511) + k_seg (blocks 512..1023).
// The two halves are data-independent; fusing lets them overlap across SMs
// instead of serializing at a kernel boundary.
// ---------------------------------------------------------------------------
#define GR 8
__global__ __launch_bounds__(256) void k_prep(const float* __restrict__ hidden,
                                              const float2* __restrict__ yp) {
    __shared__ float          sh[GR][H];          // gemmP half
    __shared__ unsigned short hist[8][49 * 33];   // k_seg half
    int t = threadIdx.x;

    if (blockIdx.x < 512) {
        // ---------------- gemmP: P[j][s*64+o] = hidden[j] . Wt[:,s*48+o] ----
        int jb = blockIdx.x * GR;
        for (int idx = t; idx < GR * H; idx += 256)
            sh[idx >> 6][idx & 63] = hidden[jb * H + idx];
        __syncthreads();

        int poff[9];
#pragma unroll
        for (int u = 0; u < 9; u++) {
            int col = u * 256 + t;
            int s = col / OD, o = col - s * OD;
            poff[u] = s * 64 + o;
        }

        float acc[GR][9];
#pragma unroll
        for (int j = 0; j < GR; j++)
#pragma unroll
            for (int u = 0; u < 9; u++) acc[j][u] = 0.f;

        for (int k = 0; k < H; k++) {
            float w[9];
#pragma unroll
            for (int u = 0; u < 9; u++) w[u] = g_Wt[k * PC + u * 256 + t];
#pragma unroll
            for (int j = 0; j < GR; j++) {
                float hv = sh[j][k];
#pragma unroll
                for (int u = 0; u < 9; u++) acc[j][u] = fmaf(hv, w[u], acc[j][u]);
            }
        }
#pragma unroll
        for (int j = 0; j < GR; j++)
#pragma unroll
            for (int u = 0; u < 9; u++)
                g_P[(size_t)(jb + j) * PCP + poff[u]] = __float2half_rn(acc[j][u]);
    } else {
        // ---------------- k_seg: g_seg[i][j] + g_invc[i][s] ----------------
        int wp = t >> 5, lane = t & 31;
        int i = (blockIdx.x - 512) * 8 + wp;
        float2 pi = yp[i];

        for (int idx = lane; idx < 49 * 33; idx += 32) hist[wp][idx] = 0;
        __syncwarp();

        unsigned char* segrow = g_seg + (size_t)i * NA;
        for (int base = 0; base < NA; base += 32) {
            float2 pj = yp[base + lane];
            int s = seg_of(pi.x, pi.y, pj.x, pj.y);
            segrow[base + lane] = (unsigned char)s;
            hist[wp][s * 33 + lane]++;          // s=48 row ignored
        }
        __syncwarp();
        for (int s = lane; s < 64; s += 32) {
            float w = 0.f;
            if (s < NSEG) {
                unsigned c = 0;
#pragma unroll
                for (int k = 0; k < 32; k++) c += hist[wp][s * 33 + k];
                w = (c > 0) ? (1.0f / (float)c) : 0.0f;
            }
            g_invc[i * 64 + s] = w;
        }
    }
}

// ---------------------------------------------------------------------------
// k_main: 4 pairs per LDG.128, batched unroll-8, one 28-warp block per SM.
// Seg ids fetched as 2 broadcast LDS.128 per 8-pair step (32B window) with
// shift/mask byte extraction — replaces 8 LDS.U8 (~15% of L1 wf bill).
// Lanes 0-23 = 4 groups of 6 (group g -> pair 4t+g, sub owns outs sub*8..+7);
// lanes 24-31 mirror group 0's lines (no extra sectors).
// ---------------------------------------------------------------------------
#define UNR 8
__global__ __launch_bounds__(IPB * 32, 1) void k_main(const float* __restrict__ fb,
                                                      float* __restrict__ out) {
    __shared__ float         wtab[IPB][64];
    __shared__ unsigned char segbuf[IPB][1024];
    int wp = threadIdx.x >> 5, lane = threadIdx.x & 31;
    int i = blockIdx.x * IPB + wp;
    if (i >= NA) return;                       // warp-uniform exit

    for (int s = lane; s < 64; s += 32) wtab[wp][s] = g_invc[i * 64 + s];
    __syncwarp();

    int grp = (lane < 24) ? (lane / 6) : 0;
    int sub = (lane < 24) ? (lane - grp * 6) : ((lane - 24) % 6);
    int shft = grp * 8;
    const unsigned char* Pb = (const unsigned char*)g_P + (unsigned)(sub * 16);

    float a0 = 0.f, a1 = 0.f, a2 = 0.f, a3 = 0.f;
    float a4 = 0.f, a5 = 0.f, a6 = 0.f, a7 = 0.f;
    const unsigned char* segrow = g_seg + (size_t)i * NA;

    for (int c0 = 0; c0 < NA; c0 += 1024) {
        const uint4* src = (const uint4*)(segrow + c0);
        uint4* dst = (uint4*)segbuf[wp];
        dst[lane]      = src[lane];
        dst[lane + 32] = src[lane + 32];
        __syncwarp();

        const unsigned char* rp = Pb + (size_t)c0 * PROWB;
        for (int t0 = 0; t0 < 256; t0 += UNR) {
            // 32 seg bytes for pairs 4*t0 .. 4*t0+31: 2 broadcast LDS.128
            const uint4* sp = (const uint4*)(segbuf[wp] + 4 * t0);
            uint4 sw0 = sp[0], sw1 = sp[1];
            int sv[UNR];
            sv[0] = (sw0.x >> shft) & 0xFF;  sv[1] = (sw0.y >> shft) & 0xFF;
            sv[2] = (sw0.z >> shft) & 0xFF;  sv[3] = (sw0.w >> shft) & 0xFF;
            sv[4] = (sw1.x >> shft) & 0xFF;  sv[5] = (sw1.y >> shft) & 0xFF;
            sv[6] = (sw1.z >> shft) & 0xFF;  sv[7] = (sw1.w >> shft) & 0xFF;
            float wv[UNR];
#pragma unroll
            for (int u = 0; u < UNR; u++)
                wv[u] = wtab[wp][sv[u]];                    // 8x LDS
            uint4 vv[UNR];
#pragma unroll
            for (int u = 0; u < UNR; u++)
                vv[u] = *(const uint4*)(rp
                          + (unsigned)(4 * (t0 + u) + grp) * PROWB
                          + ((unsigned)sv[u] << 7));        // 8x LDG.128
#pragma unroll
            for (int u = 0; u < UNR; u++) {
                float w = wv[u];
                float2 f0 = __half22float2(*(const __half2*)&vv[u].x);
                float2 f1 = __half22float2(*(const __half2*)&vv[u].y);
                float2 f2 = __half22float2(*(const __half2*)&vv[u].z);
                float2 f3 = __half22float2(*(const __half2*)&vv[u].w);
                a0 = fmaf(w, f0.x, a0); a1 = fmaf(w, f0.y, a1);
                a2 = fmaf(w, f1.x, a2); a3 = fmaf(w, f1.y, a3);
                a4 = fmaf(w, f2.x, a4); a5 = fmaf(w, f2.y, a5);
                a6 = fmaf(w, f3.x, a6); a7 = fmaf(w, f3.y, a7);
            }
        }
        __syncwarp();
    }

    // combine 4 groups: round 1 (+6) -> g0+=g1, g2+=g3; round 2 (+12)
#pragma unroll
    for (int d = 6; d <= 12; d += 6) {
        a0 += __shfl_down_sync(0xffffffffu, a0, d);
        a1 += __shfl_down_sync(0xffffffffu, a1, d);
        a2 += __shfl_down_sync(0xffffffffu, a2, d);
        a3 += __shfl_down_sync(0xffffffffu, a3, d);
        a4 += __shfl_down_sync(0xffffffffu, a4, d);
        a5 += __shfl_down_sync(0xffffffffu, a5, d);
        a6 += __shfl_down_sync(0xffffffffu, a6, d);
        a7 += __shfl_down_sync(0xffffffffu, a7, d);
    }

    if (lane < 6) {
        const float4 b0 = ((const float4*)fb)[2 * lane];
        const float4 b1 = ((const float4*)fb)[2 * lane + 1];
        float4 r0, r1;
        r0.x = fmaxf(a0 + b0.x, 0.f); r0.y = fmaxf(a1 + b0.y, 0.f);
        r0.z = fmaxf(a2 + b0.z, 0.f); r0.w = fmaxf(a3 + b0.w, 0.f);
        r1.x = fmaxf(a4 + b1.x, 0.f); r1.y = fmaxf(a5 + b1.y, 0.f);
        r1.z = fmaxf(a6 + b1.z, 0.f); r1.w = fmaxf(a7 + b1.w, 0.f);
        float* op = out + i * OD + lane * 8;
        *(float4*)op       = r0;
        *(float4*)(op + 4) = r1;
    }
}

// ---------------------------------------------------------------------------
extern "C" void kernel_launch(void* const* d_in, const int* in_sizes, int n_in,
                              void* d_out, int out_size) {
    const float* ypred  = (const float*)d_in[0];
    const float* hidden = (const float*)d_in[1];
    const float* fc_w   = (const float*)d_in[2];
    const float* fc_b   = (const float*)d_in[3];
    float* out = (float*)d_out;

    k_reshape<<<(H * PC + 255) / 256, 256>>>(fc_w);
    k_prep<<<1024, 256>>>(hidden, (const float2*)ypred);
    k_main<<<(NA + IPB - 1) / IPB, IPB * 32>>>(fc_b, out);
}